// round 5
// baseline (speedup 1.0000x reference)
#include <cuda_runtime.h>

// Problem dims
#define B_  64
#define T_  2048
#define IN_ 256
#define H_  512
#define C_  128

// Scan config: 16 clusters x 8 CTAs, 4 batches/cluster, 64 H-rows/CTA
#define CLUSTER_S 8
#define JS        64      // H_/CLUSTER_S rows of W_hh per CTA
#define GBATCH    4       // batches per cluster
#define KC        8       // k-chunks per row
#define KPT       64      // k elements per thread
#define HPAD      68      // chunk padded to 68 floats -> conflict-free LDS.128
#define SCAN_THREADS 512

// Scratch ping-pong buffers (device globals: allocation-free)
__device__ float g_bufA[(size_t)B_ * T_ * H_];
__device__ float g_bufB[(size_t)B_ * T_ * H_];

static __device__ __forceinline__ unsigned smem_u32(const void* p) {
    unsigned r;
    asm("{ .reg .u64 t; cvta.to.shared.u64 t, %1; cvt.u32.u64 %0, t; }"
        : "=r"(r) : "l"(p));
    return r;
}

// packed fp32x2 FMA: d = a*b + d
static __device__ __forceinline__ void ffma2(unsigned long long& d,
                                             unsigned long long a,
                                             unsigned long long b) {
    asm("fma.rn.f32x2 %0, %1, %2, %0;" : "+l"(d) : "l"(a), "l"(b));
}

static __device__ __forceinline__ float hadd2pair(unsigned long long a,
                                                  unsigned long long b) {
    unsigned long long s;
    asm("add.rn.f32x2 %0, %1, %2;" : "=l"(s) : "l"(a), "l"(b));
    float lo = __uint_as_float((unsigned)(s & 0xffffffffull));
    float hi = __uint_as_float((unsigned)(s >> 32));
    return lo + hi;
}

static __device__ __forceinline__ unsigned long long dupf(float f) {
    unsigned long long r;
    asm("mov.b64 %0, {%1, %1};" : "=l"(r) : "f"(f));
    return r;
}

#define MBAR_WAIT(addr, par)                                                   \
    asm volatile(                                                              \
        "{\n\t.reg .pred P;\n\t"                                               \
        "WAIT_%=:\n\t"                                                         \
        "mbarrier.try_wait.parity.acquire.cta.shared::cta.b64 P, [%0], %1, 0x989680;\n\t" \
        "@!P bra WAIT_%=;\n\t}"                                                \
        :: "r"(addr), "r"(par) : "memory")

// ---------------------------------------------------------------------------
// Recurrent scan: h_t = relu(pre_t + W_hh @ h_{t-1}).
// 16 clusters x 8 CTAs x 512 threads, tid = j*8 + kc (warp = 4 rows x 8 kc).
// W[rank*64+j][kc*64..+63] in 32 packed f32x2 regs. Hs double-buffered per
// batch; the 4 batch recurrences are INDEPENDENT, pipelined as 4 slots per
// step with per-(batch,parity) mbarriers: batch b's DSMEM broadcast latency
// hides under the compute of batches b+1..b+3 and the next step's earlier
// slots. Butterfly shuffle reduces over the 8 kc lanes (sum lands in ALL
// lanes); lane kc then ships the row value to rank kc only (1 st.async/lane).
// One __syncthreads per step keeps warps aligned. Alternating mbarriers per
// parity make tx-phase accounting exact (t+1 bytes can't credit phase t).
// ---------------------------------------------------------------------------
__global__ void __launch_bounds__(SCAN_THREADS, 1) __cluster_dims__(CLUSTER_S, 1, 1)
scan_kernel(const float* __restrict__ W_hh, const float* __restrict__ pre,
            float* __restrict__ hout, int store_all)
{
    __shared__ float Hs[2][GBATCH][KC][HPAD];          // ~17.4 KB
    __shared__ __align__(8) unsigned long long mbar[GBATCH][2];

    const int tid  = threadIdx.x;
    const int rank = blockIdx.x & (CLUSTER_S - 1);
    const int bg   = blockIdx.x >> 3;
    const int kc   = tid & 7;           // lane bits 0..2
    const int j    = tid >> 3;          // output row 0..63

    // W slice into registers: 32 packed f32x2 = 64 fp32
    unsigned long long w[KPT / 2];
    {
        const float* wsrc = W_hh + (size_t)(rank * JS + j) * H_ + kc * KPT;
        #pragma unroll
        for (int i = 0; i < KPT / 2; i++)
            w[i] = *reinterpret_cast<const unsigned long long*>(wsrc + 2 * i);
    }

    // zero both h buffers (buffer 1 is "h_{-1} = 0")
    for (int i = tid; i < 2 * GBATCH * KC * HPAD; i += SCAN_THREADS)
        (&Hs[0][0][0][0])[i] = 0.f;

    if (tid == 0) {
        #pragma unroll
        for (int b = 0; b < GBATCH; b++)
            #pragma unroll
            for (int p = 0; p < 2; p++)
                asm volatile("mbarrier.init.shared.b64 [%0], 1;"
                             :: "r"(smem_u32(&mbar[b][p])) : "memory");
    }

    // remote addresses: this lane ships (row j, batch b) to rank kc
    unsigned rH[2][GBATCH], rMB[GBATCH][2], lMB[GBATCH][2];
    #pragma unroll
    for (int b = 0; b < GBATCH; b++) {
        #pragma unroll
        for (int wb = 0; wb < 2; wb++) {
            unsigned la = smem_u32(&Hs[wb][b][rank][j]);
            asm("mapa.shared::cluster.u32 %0, %1, %2;"
                : "=r"(rH[wb][b]) : "r"(la), "r"(kc));
        }
        #pragma unroll
        for (int p = 0; p < 2; p++) {
            lMB[b][p] = smem_u32(&mbar[b][p]);
            asm("mapa.shared::cluster.u32 %0, %1, %2;"
                : "=r"(rMB[b][p]) : "r"(lMB[b][p]), "r"(kc));
        }
    }

    __syncthreads();
    asm volatile("barrier.cluster.arrive.aligned;" ::: "memory");
    asm volatile("barrier.cluster.wait.aligned;"   ::: "memory");

    // per-batch pre/hout pointers + t=0 prefetch
    const float* preP[GBATCH];
    float*       houtP[GBATCH];
    float        pv[GBATCH];
    #pragma unroll
    for (int b = 0; b < GBATCH; b++) {
        const size_t off = (size_t)(bg * GBATCH + b) * T_ * H_ + rank * JS + j;
        preP[b]  = pre  + off;
        houtP[b] = hout + off;
        pv[b]    = preP[b][0];
    }

    #pragma unroll 1
    for (int t = 0; t < T_; ++t) {
        const int wbuf = t & 1;          // write buffer (h_t)
        const int rbuf = wbuf ^ 1;       // read buffer  (h_{t-1})
        const unsigned wpar = (unsigned)((t >> 1) & 1);
        const unsigned ppar = (unsigned)(((t - 1) >> 1) & 1);

        #pragma unroll
        for (int b = 0; b < GBATCH; b++) {
            if (t > 0) MBAR_WAIT(lMB[b][(t - 1) & 1], ppar);
            if (tid == 0)
                asm volatile("mbarrier.arrive.expect_tx.shared.b64 _, [%0], %1;"
                             :: "r"(lMB[b][wbuf]), "r"(2048u) : "memory");

            // partial dot for (rows j, batch b), chunk kc
            const ulonglong2* hp =
                reinterpret_cast<const ulonglong2*>(&Hs[rbuf][b][kc][0]);
            unsigned long long a0 = 0ull, a1 = 0ull;
            #pragma unroll
            for (int i = 0; i < KPT / 4; i++) {
                ulonglong2 v = hp[i];
                ffma2(a0, w[2 * i],     v.x);
                ffma2(a1, w[2 * i + 1], v.y);
            }
            float s = hadd2pair(a0, a1);
            // butterfly over kc lanes -> full sum in every lane
            s += __shfl_xor_sync(0xffffffffu, s, 1);
            s += __shfl_xor_sync(0xffffffffu, s, 2);
            s += __shfl_xor_sync(0xffffffffu, s, 4);

            float val = fmaxf(s + pv[b], 0.f);
            asm volatile(
                "st.async.shared::cluster.mbarrier::complete_tx::bytes.b32 "
                "[%0], %1, [%2];"
                :: "r"(rH[wbuf][b]), "r"(__float_as_uint(val)),
                   "r"(rMB[b][wbuf]) : "memory");

            if (kc == 0 && (store_all || t == T_ - 1))
                houtP[b][(size_t)t * H_] = val;
            if (t + 1 < T_) pv[b] = preP[b][(size_t)(t + 1) * H_];
        }
        __syncthreads();
    }

    // drain the final step's arrivals, then cluster-exit barrier
    {
        const unsigned fpar = (unsigned)(((T_ - 1) >> 1) & 1);
        #pragma unroll
        for (int b = 0; b < GBATCH; b++)
            MBAR_WAIT(lMB[b][(T_ - 1) & 1], fpar);
    }
    asm volatile("barrier.cluster.arrive.aligned;" ::: "memory");
    asm volatile("barrier.cluster.wait.aligned;"   ::: "memory");
}

// ---------------------------------------------------------------------------
// C[M,N] = A[M,K] @ Bw[N,K]^T + bias1[N] + bias2[N]   (fp32 tiled SGEMM)
// ---------------------------------------------------------------------------
#define BM 128
#define BN 128
#define BK 8
#define TM 8
#define TN 8

__global__ void __launch_bounds__(256)
sgemm_bias_kernel(const float* __restrict__ A, const float* __restrict__ Bw,
                  const float* __restrict__ bias1, const float* __restrict__ bias2,
                  float* __restrict__ C, int M, int N, int K)
{
    __shared__ float As[BK][BM];
    __shared__ float Bs[BK][BN];

    const int tid  = threadIdx.x;
    const int bm   = blockIdx.x * BM;
    const int bn   = blockIdx.y * BN;
    const int lrow = tid >> 1;
    const int lc   = (tid & 1) * 4;
    const int tx   = tid & 15;
    const int ty   = tid >> 4;

    unsigned long long acc2[TM / 2][TN];
    #pragma unroll
    for (int i = 0; i < TM / 2; i++)
        #pragma unroll
        for (int jj = 0; jj < TN; jj++) acc2[i][jj] = 0ull;

    for (int k0 = 0; k0 < K; k0 += BK) {
        float4 av = *reinterpret_cast<const float4*>(
            &A[(size_t)(bm + lrow) * K + k0 + lc]);
        float4 bv = *reinterpret_cast<const float4*>(
            &Bw[(size_t)(bn + lrow) * K + k0 + lc]);
        __syncthreads();
        As[lc + 0][lrow] = av.x; As[lc + 1][lrow] = av.y;
        As[lc + 2][lrow] = av.z; As[lc + 3][lrow] = av.w;
        Bs[lc + 0][lrow] = bv.x; Bs[lc + 1][lrow] = bv.y;
        Bs[lc + 2][lrow] = bv.z; Bs[lc + 3][lrow] = bv.w;
        __syncthreads();

        #pragma unroll
        for (int kk = 0; kk < BK; ++kk) {
            ulonglong2 raA = *reinterpret_cast<const ulonglong2*>(&As[kk][ty * TM]);
            ulonglong2 raB = *reinterpret_cast<const ulonglong2*>(&As[kk][ty * TM + 4]);
            float4 rb0 = *reinterpret_cast<const float4*>(&Bs[kk][tx * TN]);
            float4 rb1 = *reinterpret_cast<const float4*>(&Bs[kk][tx * TN + 4]);
            unsigned long long ra[4] = { raA.x, raA.y, raB.x, raB.y };
            unsigned long long rbb[8];
            rbb[0] = dupf(rb0.x); rbb[1] = dupf(rb0.y);
            rbb[2] = dupf(rb0.z); rbb[3] = dupf(rb0.w);
            rbb[4] = dupf(rb1.x); rbb[5] = dupf(rb1.y);
            rbb[6] = dupf(rb1.z); rbb[7] = dupf(rb1.w);
            #pragma unroll
            for (int i2 = 0; i2 < 4; ++i2)
                #pragma unroll
                for (int jj = 0; jj < TN; ++jj)
                    ffma2(acc2[i2][jj], ra[i2], rbb[jj]);
        }
    }

    #pragma unroll
    for (int i2 = 0; i2 < TM / 2; ++i2) {
        const size_t row0 = (size_t)(bm + ty * TM + 2 * i2) * N;
        const size_t row1 = row0 + N;
        #pragma unroll
        for (int jj = 0; jj < TN; ++jj) {
            const int col = bn + tx * TN + jj;
            float lo = __uint_as_float((unsigned)(acc2[i2][jj] & 0xffffffffull));
            float hi = __uint_as_float((unsigned)(acc2[i2][jj] >> 32));
            float bsum = bias1[col] + bias2[col];
            C[row0 + col] = lo + bsum;
            C[row1 + col] = hi + bsum;
        }
    }
}

// ---------------------------------------------------------------------------
// out[b,c] = h1[b, T-1, :] . fc_w[c, :] + fc_b[c]
// ---------------------------------------------------------------------------
__global__ void __launch_bounds__(C_)
fc_kernel(const float* __restrict__ h, const float* __restrict__ fw,
          const float* __restrict__ fb, float* __restrict__ out)
{
    __shared__ float hv[H_];
    const int b = blockIdx.x;
    const int c = threadIdx.x;
    for (int k = c; k < H_; k += C_)
        hv[k] = h[((size_t)b * T_ + (T_ - 1)) * H_ + k];
    __syncthreads();

    const float* w = fw + (size_t)c * H_;
    float acc = 0.f;
    #pragma unroll 8
    for (int k = 0; k < H_; k += 4) {
        float4 wv = *reinterpret_cast<const float4*>(w + k);
        acc += wv.x * hv[k] + wv.y * hv[k + 1] + wv.z * hv[k + 2] + wv.w * hv[k + 3];
    }
    out[b * C_ + c] = acc + fb[c];
}

// ---------------------------------------------------------------------------
extern "C" void kernel_launch(void* const* d_in, const int* in_sizes, int n_in,
                              void* d_out, int out_size)
{
    const float* x     = (const float*)d_in[0];
    const float* W_ih0 = (const float*)d_in[1];
    const float* W_hh0 = (const float*)d_in[2];
    const float* b_ih0 = (const float*)d_in[3];
    const float* b_hh0 = (const float*)d_in[4];
    const float* W_ih1 = (const float*)d_in[5];
    const float* W_hh1 = (const float*)d_in[6];
    const float* b_ih1 = (const float*)d_in[7];
    const float* b_hh1 = (const float*)d_in[8];
    const float* fc_w  = (const float*)d_in[9];
    const float* fc_b  = (const float*)d_in[10];
    float* out = (float*)d_out;

    float *bufA, *bufB;
    cudaGetSymbolAddress((void**)&bufA, g_bufA);
    cudaGetSymbolAddress((void**)&bufB, g_bufB);

    const int M = B_ * T_;
    dim3 gemm_grid(M / BM, H_ / BN);

    // pre0 = x @ W_ih0^T + b_ih0 + b_hh0
    sgemm_bias_kernel<<<gemm_grid, 256>>>(x, W_ih0, b_ih0, b_hh0, bufA,
                                          M, H_, IN_);
    // layer 0 scan: bufA(pre) -> bufB(h0), full stream-out
    scan_kernel<<<dim3(16 * CLUSTER_S), SCAN_THREADS>>>(W_hh0, bufA, bufB, 1);
    // pre1 = h0 @ W_ih1^T + b_ih1 + b_hh1
    sgemm_bias_kernel<<<gemm_grid, 256>>>(bufB, W_ih1, b_ih1, b_hh1, bufA,
                                          M, H_, H_);
    // layer 1 scan: bufA(pre) -> bufA, only t = T-1 written
    scan_kernel<<<dim3(16 * CLUSTER_S), SCAN_THREADS>>>(W_hh1, bufA, bufA, 0);
    // out = h1[:, -1, :] @ fc_w^T + fc_b
    fc_kernel<<<B_, C_>>>(bufA, fc_w, fc_b, out);
}